// round 17
// baseline (speedup 1.0000x reference)
#include <cuda_runtime.h>
#include <cuda_bf16.h>
#include <cstdint>

#define NSEG   10000
#define D      128
#define BMT    128                        // segments per mma tile block
#define NBLK_G ((NSEG + BMT - 1) / BMT)   // 79
#define LDT    136                        // bf16 row stride (pad: conflict-free frags)

// smem (bytes): a_hi, a_lo, b_hi, b_lo each 128*136*2 = 34816
#define OFF_AH 0
#define OFF_AL 34816
#define OFF_BH 69632
#define OFF_BL 104448
#define SMEM_G 139264

__device__ float g_sumsA[NSEG * D];
__device__ float g_sumsB[NSEG * D];

// graph may be int32 or int64 depending on jax x64 config.
__device__ __forceinline__ void load_seg(const int* __restrict__ g, int s,
                                         int& st, int& en) {
    bool is64 = (g[2 * NSEG - 1] == 0);
    if (is64) { st = g[4 * s];  en = g[4 * s + 2]; }
    else      { st = g[2 * s];  en = g[2 * s + 1]; }
}

// pack2(lo, hi): b32 = {hi[31:16], lo[15:0]} as bf16
__device__ __forceinline__ uint32_t pack2(float lo, float hi) {
    uint32_t r;
    asm("cvt.rn.bf16x2.f32 %0, %1, %2;" : "=r"(r) : "f"(hi), "f"(lo));
    return r;
}

__device__ __forceinline__ void mma_bf16(float* c, const uint32_t* a,
                                         uint32_t b0, uint32_t b1) {
    asm volatile(
        "mma.sync.aligned.m16n8k16.row.col.f32.bf16.bf16.f32 "
        "{%0,%1,%2,%3}, {%4,%5,%6,%7}, {%8,%9}, {%0,%1,%2,%3};"
        : "+f"(c[0]), "+f"(c[1]), "+f"(c[2]), "+f"(c[3])
        : "r"(a[0]), "r"(a[1]), "r"(a[2]), "r"(a[3]), "r"(b0), "r"(b1));
}

// ---------------------------------------------------------------------------
// Kernel 1: R16 sum (protected). Two blocks per segment -> g_sumsA/B.
// ---------------------------------------------------------------------------
__global__ void __launch_bounds__(128) sum_kernel(
    const float* __restrict__ input,
    const int*   __restrict__ graph)
{
    const int s    = blockIdx.x >> 1;
    const int h    = blockIdx.x & 1;
    const int c4   = threadIdx.x & 31;
    const int rl   = threadIdx.x >> 5;

    int start, end;
    load_seg(graph, s, start, end);
    const int nfull = end - start + 1;
    const int n0    = (nfull + 1) >> 1;

    const int hstart = h ? (start + n0) : start;
    const int n      = h ? (nfull - n0) : n0;
    float* dst = (h ? g_sumsB : g_sumsA) + s * D;

    float4 acc = make_float4(0.f, 0.f, 0.f, 0.f);
    if (n > 0) {
        const float4* base = (const float4*)input + (long long)hstart * 32 + c4;
        int r = rl;
        for (; r + 12 < n; r += 16) {
            const float4* p = base + (long long)r * 32;
            float4 v0 = p[0 * 32];
            float4 v1 = p[4 * 32];
            float4 v2 = p[8 * 32];
            float4 v3 = p[12 * 32];
            acc.x += (v0.x + v1.x) + (v2.x + v3.x);
            acc.y += (v0.y + v1.y) + (v2.y + v3.y);
            acc.z += (v0.z + v1.z) + (v2.z + v3.z);
            acc.w += (v0.w + v1.w) + (v2.w + v3.w);
        }
        for (; r < n; r += 4) {
            float4 v = base[(long long)r * 32];
            acc.x += v.x; acc.y += v.y; acc.z += v.z; acc.w += v.w;
        }
    }

    __shared__ float4 red[4][32];
    red[rl][c4] = acc;
    __syncthreads();
    if (rl == 0) {
        float4 a = red[0][c4], b2 = red[1][c4], c = red[2][c4], d = red[3][c4];
        float4 t;
        t.x = (a.x + b2.x) + (c.x + d.x);
        t.y = (a.y + b2.y) + (c.y + d.y);
        t.z = (a.z + b2.z) + (c.z + d.z);
        t.w = (a.w + b2.w) + (c.w + d.w);
        ((float4*)dst)[c4] = t;
    }
}

// ---------------------------------------------------------------------------
// Kernel 2: mma.sync bf16 hi/lo GEMM. 79 blocks x 256 threads.
// Block = 128 segments; warp w owns m-strip [16w,16w+16), full N=128.
// A = sums (hi+lo bf16 smem), B = W[n][k] (hi+lo bf16 smem, col layout
// native). D = Ah*Bh + Ah*Bl + Al*Bh in fp32 accs. + count*b epilogue.
// PDL: W staging before the grid dependency; x staging after.
// ---------------------------------------------------------------------------
__global__ void __launch_bounds__(256) mma_gemm_kernel(
    const int*   __restrict__ graph,
    const float* __restrict__ W,
    const float* __restrict__ b,
    float*       __restrict__ out)
{
    extern __shared__ char sm[];
    __nv_bfloat16* a_hi = (__nv_bfloat16*)(sm + OFF_AH);
    __nv_bfloat16* a_lo = (__nv_bfloat16*)(sm + OFF_AL);
    __nv_bfloat16* b_hi = (__nv_bfloat16*)(sm + OFF_BH);
    __nv_bfloat16* b_lo = (__nv_bfloat16*)(sm + OFF_BL);

    const int tid = threadIdx.x;
    const int m0  = blockIdx.x * BMT;

    // --- Stage B = W (hi/lo) — independent of the sum kernel (PDL overlap) --
    for (int lin = tid; lin < D * 32; lin += 256) {
        int n = lin >> 5;
        int j = lin & 31;                 // k = 4j..4j+3
        float4 w = __ldg((const float4*)W + n * 32 + j);
        __nv_bfloat16 hx = __float2bfloat16(w.x), hy = __float2bfloat16(w.y);
        __nv_bfloat16 hz = __float2bfloat16(w.z), hw = __float2bfloat16(w.w);
        uint32_t H0 = (uint32_t)__bfloat16_as_ushort(hx) |
                      ((uint32_t)__bfloat16_as_ushort(hy) << 16);
        uint32_t H1 = (uint32_t)__bfloat16_as_ushort(hz) |
                      ((uint32_t)__bfloat16_as_ushort(hw) << 16);
        uint32_t L0 = pack2(w.x - __bfloat162float(hx),
                            w.y - __bfloat162float(hy));
        uint32_t L1 = pack2(w.z - __bfloat162float(hz),
                            w.w - __bfloat162float(hw));
        int off = n * LDT + 4 * j;        // bf16 units, 8B-aligned stores
        *(uint2*)(b_hi + off) = make_uint2(H0, H1);
        *(uint2*)(b_lo + off) = make_uint2(L0, L1);
    }

    cudaGridDependencySynchronize();

    // --- Stage A = sumsA+sumsB (hi/lo) --------------------------------------
    for (int lin = tid; lin < BMT * 32; lin += 256) {
        int m = lin >> 5;
        int j = lin & 31;
        int seg = m0 + m;
        float4 v = make_float4(0.f, 0.f, 0.f, 0.f);
        if (seg < NSEG) {
            float4 va = ((const float4*)g_sumsA)[seg * 32 + j];
            float4 vb = ((const float4*)g_sumsB)[seg * 32 + j];
            v.x = va.x + vb.x; v.y = va.y + vb.y;
            v.z = va.z + vb.z; v.w = va.w + vb.w;
        }
        __nv_bfloat16 hx = __float2bfloat16(v.x), hy = __float2bfloat16(v.y);
        __nv_bfloat16 hz = __float2bfloat16(v.z), hw = __float2bfloat16(v.w);
        uint32_t H0 = (uint32_t)__bfloat16_as_ushort(hx) |
                      ((uint32_t)__bfloat16_as_ushort(hy) << 16);
        uint32_t H1 = (uint32_t)__bfloat16_as_ushort(hz) |
                      ((uint32_t)__bfloat16_as_ushort(hw) << 16);
        uint32_t L0 = pack2(v.x - __bfloat162float(hx),
                            v.y - __bfloat162float(hy));
        uint32_t L1 = pack2(v.z - __bfloat162float(hz),
                            v.w - __bfloat162float(hw));
        int off = m * LDT + 4 * j;
        *(uint2*)(a_hi + off) = make_uint2(H0, H1);
        *(uint2*)(a_lo + off) = make_uint2(L0, L1);
    }
    __syncthreads();

    // --- MMA mainloop --------------------------------------------------------
    const int wid  = tid >> 5;
    const int lane = tid & 31;
    const int q    = lane >> 2;          // 0..7
    const int r2   = (lane & 3) * 2;     // 0,2,4,6
    const int ms   = wid * 16;

    float acc[16][4];
#pragma unroll
    for (int i = 0; i < 16; i++)
#pragma unroll
        for (int j = 0; j < 4; j++) acc[i][j] = 0.f;

    const char* ah_c = (const char*)a_hi;
    const char* al_c = (const char*)a_lo;
    const char* bh_c = (const char*)b_hi;
    const char* bl_c = (const char*)b_lo;

#pragma unroll
    for (int kc = 0; kc < 8; kc++) {
        const int k0 = kc * 16;
        const int rA0 = (ms + q)     * LDT;
        const int rA1 = (ms + q + 8) * LDT;
        uint32_t ah[4], al[4];
        ah[0] = *(const uint32_t*)(ah_c + 2 * (rA0 + k0 + r2));
        ah[1] = *(const uint32_t*)(ah_c + 2 * (rA1 + k0 + r2));
        ah[2] = *(const uint32_t*)(ah_c + 2 * (rA0 + k0 + r2 + 8));
        ah[3] = *(const uint32_t*)(ah_c + 2 * (rA1 + k0 + r2 + 8));
        al[0] = *(const uint32_t*)(al_c + 2 * (rA0 + k0 + r2));
        al[1] = *(const uint32_t*)(al_c + 2 * (rA1 + k0 + r2));
        al[2] = *(const uint32_t*)(al_c + 2 * (rA0 + k0 + r2 + 8));
        al[3] = *(const uint32_t*)(al_c + 2 * (rA1 + k0 + r2 + 8));

#pragma unroll
        for (int nt = 0; nt < 16; nt++) {
            const int rB = (nt * 8 + q) * LDT;
            uint32_t bh0 = *(const uint32_t*)(bh_c + 2 * (rB + k0 + r2));
            uint32_t bh1 = *(const uint32_t*)(bh_c + 2 * (rB + k0 + r2 + 8));
            uint32_t bl0 = *(const uint32_t*)(bl_c + 2 * (rB + k0 + r2));
            uint32_t bl1 = *(const uint32_t*)(bl_c + 2 * (rB + k0 + r2 + 8));
            mma_bf16(acc[nt], ah, bh0, bh1);
            mma_bf16(acc[nt], ah, bl0, bl1);
            mma_bf16(acc[nt], al, bh0, bh1);
        }
    }

    // --- Epilogue: + count * b, direct STG.64 -------------------------------
    const int seg0 = m0 + ms + q;
    const int seg1 = seg0 + 8;
    float cnt0 = 0.f, cnt1 = 0.f;
    if (seg0 < NSEG) { int st, en; load_seg(graph, seg0, st, en); cnt0 = (float)(en - st + 1); }
    if (seg1 < NSEG) { int st, en; load_seg(graph, seg1, st, en); cnt1 = (float)(en - st + 1); }

#pragma unroll
    for (int nt = 0; nt < 16; nt++) {
        const int n0 = nt * 8 + r2;
        float bv0 = __ldg(b + n0);
        float bv1 = __ldg(b + n0 + 1);
        if (seg0 < NSEG) {
            float2 o = make_float2(acc[nt][0] + cnt0 * bv0,
                                   acc[nt][1] + cnt0 * bv1);
            *(float2*)(out + (long long)seg0 * D + n0) = o;
        }
        if (seg1 < NSEG) {
            float2 o = make_float2(acc[nt][2] + cnt1 * bv0,
                                   acc[nt][3] + cnt1 * bv1);
            *(float2*)(out + (long long)seg1 * D + n0) = o;
        }
    }
}

extern "C" void kernel_launch(void* const* d_in, const int* in_sizes, int n_in,
                              void* d_out, int out_size) {
    const float* input = (const float*)d_in[0];
    const int*   graph = (const int*)  d_in[1];
    const float* W     = (const float*)d_in[2];
    const float* b     = (const float*)d_in[3];
    float*       out   = (float*)d_out;

    cudaFuncSetAttribute(mma_gemm_kernel,
                         cudaFuncAttributeMaxDynamicSharedMemorySize, SMEM_G);

    sum_kernel<<<2 * NSEG, 128>>>(input, graph);

    cudaLaunchConfig_t cfg = {};
    cfg.gridDim          = dim3(NBLK_G, 1, 1);
    cfg.blockDim         = dim3(256, 1, 1);
    cfg.dynamicSmemBytes = SMEM_G;
    cfg.stream           = 0;
    cudaLaunchAttribute attrs[1];
    attrs[0].id = cudaLaunchAttributeProgrammaticStreamSerialization;
    attrs[0].val.programmaticStreamSerializationAllowed = 1;
    cfg.attrs    = attrs;
    cfg.numAttrs = 1;
    cudaLaunchKernelEx(&cfg, mma_gemm_kernel, graph, W, b, out);
}